// round 12
// baseline (speedup 1.0000x reference)
#include <cuda_runtime.h>
#include <cuda_fp16.h>

#define NN 50000
#define EE 800000
#define RR 2
#define DD 128
#define GG 64
#define CC 8
#define NBLK ((NN + 255) / 256)   // 196
#define E4 (EE / 4)               // 200000

// ---------------- scratch ----------------------------------------------------
// NOTE: g_deg and g_gsum rely on a cross-launch invariant: statically
// zero-initialized at module load, and re-zeroed by pool2 at the END of every
// kernel_launch. Deterministic: every call sees them zeroed on entry.
__device__ __half g_xh[NN * DD];         // fp16 x; later reused for final h
__device__ __half g_hh[NN * DD];         // fp16 layer-1 activations
__device__ __half g_zh[RR][NN * DD];     // per-relation aggregated (fp16)
__device__ __half g_WhT[RR * 2][DD * DD];// fp16 transposed weights [n][k]
__device__ float  g_inv[RR][NN];
__device__ int    g_deg[RR][NN];         // zeroed by pool2 (invariant)
__device__ int    g_rowptr[RR][NN];      // per-node region begin
__device__ int    g_fill[RR][NN];        // fill cursor; == region end after fill
__device__ int2   g_edge[RR][EE];        // {src, float norm}
__device__ int    g_cursor[RR];          // region allocation cursors
__device__ float  g_gsum[GG * DD];       // pooled partial sums (zeroed by pool2)

// ---------------- 1. prep: convert x + W, count degrees, reset cursors -------
__global__ void prep_kernel(const float* __restrict__ x, const float* __restrict__ W,
                            const int* __restrict__ ei) {
    int i = blockIdx.x * blockDim.x + threadIdx.x;
    if (i < 2) g_cursor[i] = 0;
    if (i < NN * DD / 4) {
        float4 v = ((const float4*)x)[i];
        __half2 a = __floats2half2_rn(v.x, v.y);
        __half2 b = __floats2half2_rn(v.z, v.w);
        uint2 o;
        o.x = *(unsigned*)&a;
        o.y = *(unsigned*)&b;
        ((uint2*)g_xh)[i] = o;
    }
    if (i < 4 * DD * DD) {   // W [L,R,D,D] (k,n) -> WhT[lr][n*D+k]
        int lr = i >> 14, rem = i & 16383, k = rem >> 7, n = rem & 127;
        g_WhT[lr][n * DD + k] = __float2half(W[i]);
    }
    if (i < RR * E4) {       // degree count (g_deg zeroed by invariant)
        int r = i / E4, e4 = i % E4;
        int4 d = __ldg(&((const int4*)(ei + r * 2 * EE + EE))[e4]);
        atomicAdd(&g_deg[r][d.x], 1);
        atomicAdd(&g_deg[r][d.y], 1);
        atomicAdd(&g_deg[r][d.z], 1);
        atomicAdd(&g_deg[r][d.w], 1);
    }
}

// ---------------- 2. local scan: inv sqrt + block-local CSR regions ----------
// Each block prefix-scans its 256 degrees and claims a contiguous edge region
// with one atomicAdd; per-node ranges are contiguous (global order arbitrary).
__global__ void scanlocal_kernel() {
    int r = blockIdx.y, blk = blockIdx.x, t = threadIdx.x;
    int idx = blk * 256 + t;
    int v = (idx < NN) ? g_deg[r][idx] : 0;
    if (idx < NN) g_inv[r][idx] = rsqrtf((float)v + 1.0f);

    int lane = t & 31, w = t >> 5;
    int x = v;
    #pragma unroll
    for (int o = 1; o < 32; o <<= 1) {
        int y = __shfl_up_sync(~0u, x, o);
        if (lane >= o) x += y;
    }
    __shared__ int wsum[8];
    __shared__ int sbase;
    if (lane == 31) wsum[w] = x;
    __syncthreads();
    if (t == 0) {
        int run = 0;
        #pragma unroll
        for (int i = 0; i < 8; i++) { int tmp = wsum[i]; wsum[i] = run; run += tmp; }
        sbase = atomicAdd(&g_cursor[r], run);
    }
    __syncthreads();
    int exc = x - v + wsum[w] + sbase;
    if (idx < NN) { g_rowptr[r][idx] = exc; g_fill[r][idx] = exc; }
}

// ---------------- 3. fill CSR (4 edges / thread) -----------------------------
__global__ void fill_csr_kernel(const int* __restrict__ ei) {
    int idx = blockIdx.x * blockDim.x + threadIdx.x;
    if (idx >= RR * E4) return;
    int r = idx / E4, e4 = idx % E4;
    int4 s = __ldg(&((const int4*)(ei + r * 2 * EE))[e4]);
    int4 d = __ldg(&((const int4*)(ei + r * 2 * EE + EE))[e4]);
    const float* inv = g_inv[r];
    int2* ed = g_edge[r];
    int p;
    p = atomicAdd(&g_fill[r][d.x], 1);
    ed[p] = make_int2(s.x, __float_as_int(inv[s.x] * inv[d.x]));
    p = atomicAdd(&g_fill[r][d.y], 1);
    ed[p] = make_int2(s.y, __float_as_int(inv[s.y] * inv[d.y]));
    p = atomicAdd(&g_fill[r][d.z], 1);
    ed[p] = make_int2(s.z, __float_as_int(inv[s.z] * inv[d.z]));
    p = atomicAdd(&g_fill[r][d.w], 1);
    ed[p] = make_int2(s.w, __float_as_int(inv[s.w] * inv[d.w]));
}

// ---------------- 4/6. aggregation: z_r = A_r_norm h + d^-1 h ----------------
// One warp per dst node; lane owns 4 channels; fp32 FFMA accumulate, fp16 store.
// Feature gathers: __ldcg (L2-only). Edge stream: int4 (2 edges per load,
// broadcast) -> 2.5 wavefronts/edge instead of 3.
__global__ __launch_bounds__(256) void agg_kernel(const __half* __restrict__ h) {
    int r = blockIdx.y;
    int gw = (blockIdx.x * blockDim.x + threadIdx.x) >> 5;
    int lane = threadIdx.x & 31;
    if (gw >= NN) return;
    const uint2* hv = (const uint2*)h;
    const int2* ed = g_edge[r];
    const int4* ed4 = (const int4*)ed;
    float4 acc = make_float4(0.f, 0.f, 0.f, 0.f);
    int beg = g_rowptr[r][gw], end = g_fill[r][gw];
    int e = beg;

    // lead-in single edge to reach int4 (pair) alignment
    if (e < end && (e & 1)) {
        int2 p = __ldcs(&ed[e]);
        uint2 v = __ldcg(&hv[p.x * 32 + lane]);
        float nm = __int_as_float(p.y);
        float2 fa = __half22float2(*(__half2*)&v.x);
        float2 fb = __half22float2(*(__half2*)&v.y);
        acc.x = fmaf(nm, fa.x, acc.x);
        acc.y = fmaf(nm, fa.y, acc.y);
        acc.z = fmaf(nm, fb.x, acc.z);
        acc.w = fmaf(nm, fb.y, acc.w);
        e++;
    }
    // 8 edges (4 int4 pair-loads) per iteration; fp32 math
    for (; e + 8 <= end; e += 8) {
        int4 q[4]; uint2 v[8];
        #pragma unroll
        for (int u = 0; u < 4; u++) q[u] = __ldcs(&ed4[(e >> 1) + u]);
        #pragma unroll
        for (int u = 0; u < 4; u++) {
            v[2 * u]     = __ldcg(&hv[q[u].x * 32 + lane]);
            v[2 * u + 1] = __ldcg(&hv[q[u].z * 32 + lane]);
        }
        #pragma unroll
        for (int u = 0; u < 4; u++) {
            float n0 = __int_as_float(q[u].y);
            float n1 = __int_as_float(q[u].w);
            float2 a0 = __half22float2(*(__half2*)&v[2 * u].x);
            float2 b0 = __half22float2(*(__half2*)&v[2 * u].y);
            float2 a1 = __half22float2(*(__half2*)&v[2 * u + 1].x);
            float2 b1 = __half22float2(*(__half2*)&v[2 * u + 1].y);
            acc.x = fmaf(n0, a0.x, fmaf(n1, a1.x, acc.x));
            acc.y = fmaf(n0, a0.y, fmaf(n1, a1.y, acc.y));
            acc.z = fmaf(n0, b0.x, fmaf(n1, b1.x, acc.z));
            acc.w = fmaf(n0, b0.y, fmaf(n1, b1.y, acc.w));
        }
    }
    // remaining pairs
    for (; e + 2 <= end; e += 2) {
        int4 q = __ldcs(&ed4[e >> 1]);
        uint2 v0 = __ldcg(&hv[q.x * 32 + lane]);
        uint2 v1 = __ldcg(&hv[q.z * 32 + lane]);
        float n0 = __int_as_float(q.y), n1 = __int_as_float(q.w);
        float2 a0 = __half22float2(*(__half2*)&v0.x), b0 = __half22float2(*(__half2*)&v0.y);
        float2 a1 = __half22float2(*(__half2*)&v1.x), b1 = __half22float2(*(__half2*)&v1.y);
        acc.x = fmaf(n0, a0.x, fmaf(n1, a1.x, acc.x));
        acc.y = fmaf(n0, a0.y, fmaf(n1, a1.y, acc.y));
        acc.z = fmaf(n0, b0.x, fmaf(n1, b1.x, acc.z));
        acc.w = fmaf(n0, b0.y, fmaf(n1, b1.y, acc.w));
    }
    // trailing single
    if (e < end) {
        int2 p = __ldcs(&ed[e]);
        uint2 v = __ldcg(&hv[p.x * 32 + lane]);
        float nm = __int_as_float(p.y);
        float2 fa = __half22float2(*(__half2*)&v.x);
        float2 fb = __half22float2(*(__half2*)&v.y);
        acc.x = fmaf(nm, fa.x, acc.x);
        acc.y = fmaf(nm, fa.y, acc.y);
        acc.z = fmaf(nm, fb.x, acc.z);
        acc.w = fmaf(nm, fb.y, acc.w);
    }
    // self loop
    float iv = g_inv[r][gw];
    float self = iv * iv;
    uint2 v = __ldg(&hv[gw * 32 + lane]);
    float2 fa = __half22float2(*(__half2*)&v.x);
    float2 fb = __half22float2(*(__half2*)&v.y);
    acc.x = fmaf(self, fa.x, acc.x);
    acc.y = fmaf(self, fa.y, acc.y);
    acc.z = fmaf(self, fb.x, acc.z);
    acc.w = fmaf(self, fb.y, acc.w);
    __half2 o0 = __floats2half2_rn(acc.x, acc.y);
    __half2 o1 = __floats2half2_rn(acc.z, acc.w);
    uint2 o;
    o.x = *(unsigned*)&o0;
    o.y = *(unsigned*)&o1;
    ((uint2*)g_zh[r])[gw * 32 + lane] = o;
}

// ---------------- 5/7. fused dual tensor-core GEMM (+ optional pool) ---------
__global__ __launch_bounds__(256) void gemm_dual_mma(
    const __half* __restrict__ WT0, const __half* __restrict__ WT1,
    const float* __restrict__ b0, const float* __restrict__ b1,
    const __half* __restrict__ zh0, const __half* __restrict__ zh1,
    __half* __restrict__ outh, int do_relu, const int* __restrict__ batch)
{
    __shared__ __half SBUF[2 * 128 * 72];   // As | Bs ; reused as h tile for pool
    __half (*As)[72] = (__half(*)[72])SBUF;
    __half (*Bs)[72] = (__half(*)[72])(SBUF + 128 * 72);
    int t = threadIdx.x;
    int warp = t >> 5, lane = t & 31;
    int wm = warp & 3, wn = warp >> 2;
    int g = lane >> 2, tg = lane & 3;
    int row0 = blockIdx.x * 128;

    float acc[2][8][4];
    #pragma unroll
    for (int mt = 0; mt < 2; mt++)
        #pragma unroll
        for (int nt = 0; nt < 8; nt++)
            #pragma unroll
            for (int q = 0; q < 4; q++) acc[mt][nt][q] = 0.f;

    #pragma unroll
    for (int phase = 0; phase < 2; phase++) {
        const __half* Z  = phase ? zh1 : zh0;
        const __half* WT = phase ? WT1 : WT0;
        #pragma unroll
        for (int kc = 0; kc < 128; kc += 64) {
            __syncthreads();
            for (int i = t; i < 128 * 8; i += 256) {
                int row = i >> 3, c8 = (i & 7) * 8;
                uint4 v = make_uint4(0, 0, 0, 0);
                int gr = row0 + row;
                if (gr < NN) v = *(const uint4*)&Z[gr * 128 + kc + c8];
                *(uint4*)&As[row][c8] = v;
            }
            for (int i = t; i < 128 * 8; i += 256) {
                int n = i >> 3, c8 = (i & 7) * 8;
                *(uint4*)&Bs[n][c8] = *(const uint4*)&WT[n * 128 + kc + c8];
            }
            __syncthreads();
            #pragma unroll
            for (int kk = 0; kk < 4; kk++) {
                int k0 = kk * 16;
                unsigned a[2][4];
                #pragma unroll
                for (int mt = 0; mt < 2; mt++) {
                    int rb = wm * 32 + mt * 16;
                    a[mt][0] = *(unsigned*)&As[rb + g][k0 + tg * 2];
                    a[mt][1] = *(unsigned*)&As[rb + g + 8][k0 + tg * 2];
                    a[mt][2] = *(unsigned*)&As[rb + g][k0 + tg * 2 + 8];
                    a[mt][3] = *(unsigned*)&As[rb + g + 8][k0 + tg * 2 + 8];
                }
                #pragma unroll
                for (int nt = 0; nt < 8; nt++) {
                    int cb = wn * 64 + nt * 8 + g;
                    unsigned bf0 = *(unsigned*)&Bs[cb][k0 + tg * 2];
                    unsigned bf1 = *(unsigned*)&Bs[cb][k0 + tg * 2 + 8];
                    #pragma unroll
                    for (int mt = 0; mt < 2; mt++) {
                        asm volatile(
                            "mma.sync.aligned.m16n8k16.row.col.f32.f16.f16.f32 "
                            "{%0,%1,%2,%3}, {%4,%5,%6,%7}, {%8,%9}, {%0,%1,%2,%3};\n"
                            : "+f"(acc[mt][nt][0]), "+f"(acc[mt][nt][1]),
                              "+f"(acc[mt][nt][2]), "+f"(acc[mt][nt][3])
                            : "r"(a[mt][0]), "r"(a[mt][1]), "r"(a[mt][2]), "r"(a[mt][3]),
                              "r"(bf0), "r"(bf1));
                    }
                }
            }
        }
    }
    if (batch) __syncthreads();

    #pragma unroll
    for (int mt = 0; mt < 2; mt++) {
        int rl = wm * 32 + mt * 16 + g;
        int r_lo = row0 + rl;
        int r_hi = r_lo + 8;
        #pragma unroll
        for (int nt = 0; nt < 8; nt++) {
            int c = wn * 64 + nt * 8 + tg * 2;
            float bia0 = b0[c] + b1[c];
            float bia1 = b0[c + 1] + b1[c + 1];
            float v0 = acc[mt][nt][0] + bia0;
            float v1 = acc[mt][nt][1] + bia1;
            float v2 = acc[mt][nt][2] + bia0;
            float v3 = acc[mt][nt][3] + bia1;
            if (do_relu) {
                v0 = fmaxf(v0, 0.f); v1 = fmaxf(v1, 0.f);
                v2 = fmaxf(v2, 0.f); v3 = fmaxf(v3, 0.f);
            }
            __half2 plo = __floats2half2_rn(v0, v1);
            __half2 phi = __floats2half2_rn(v2, v3);
            if (r_lo < NN) *(__half2*)&outh[r_lo * 128 + c] = plo;
            if (r_hi < NN) *(__half2*)&outh[r_hi * 128 + c] = phi;
            if (batch) {
                *(__half2*)&SBUF[rl * 130 + c] = plo;
                *(__half2*)&SBUF[(rl + 8) * 130 + c] = phi;
            }
        }
    }
    if (batch) {
        __syncthreads();
        if (t < DD) {
            int row_end = (row0 + 128 > NN) ? (NN - row0) : 128;
            float run = 0.f;
            int cur = __ldg(&batch[row0]);
            for (int rl = 0; rl < row_end; rl++) {
                int gid = __ldg(&batch[row0 + rl]);
                if (gid != cur) {
                    atomicAdd(&g_gsum[cur * DD + t], run);
                    run = 0.f;
                    cur = gid;
                }
                run += __half2float(SBUF[rl * 130 + t]);
            }
            atomicAdd(&g_gsum[cur * DD + t], run);
        }
    }
}

// ---------------- 8. pool finalize + head + re-zero invariants ---------------
__global__ void pool2_kernel(const int* __restrict__ batch,
                             const float* __restrict__ lw, const float* __restrict__ lb,
                             float* __restrict__ out) {
    int g = blockIdx.x;
    int t = threadIdx.x;
    int lo = 0, hi = NN;
    while (lo < hi) { int m = (lo + hi) >> 1; if (batch[m] < g) lo = m + 1; else hi = m; }
    int beg = lo;
    lo = beg; hi = NN;
    while (lo < hi) { int m = (lo + hi) >> 1; if (batch[m] < g + 1) lo = m + 1; else hi = m; }
    int cnt = lo - beg;

    __shared__ float pooled[DD];
    float s = g_gsum[g * DD + t];
    g_gsum[g * DD + t] = 0.f;              // re-zero own slot (invariant)
    pooled[t] = s / fmaxf((float)cnt, 1.0f);
    __syncthreads();
    if (t < CC) {
        float o = lb[t];
        #pragma unroll 16
        for (int d = 0; d < DD; d++) o = fmaf(pooled[d], lw[d * CC + t], o);
        out[g * CC + t] = o;
    }
    // re-zero degree counters for next launch (disjoint from reads above)
    for (int i = blockIdx.x * blockDim.x + t; i < RR * NN; i += GG * DD)
        ((int*)g_deg)[i] = 0;
}

// ---------------- host launch -------------------------------------------------
extern "C" void kernel_launch(void* const* d_in, const int* in_sizes, int n_in,
                              void* d_out, int out_size)
{
    const float* x     = (const float*)d_in[0];
    const float* W     = (const float*)d_in[1];
    const float* b     = (const float*)d_in[2];
    const float* lin_w = (const float*)d_in[3];
    const float* lin_b = (const float*)d_in[4];
    const int*   ei    = (const int*)d_in[5];
    const int*   batch = (const int*)d_in[6];
    float* out = (float*)d_out;

    __half* d_xh;  cudaGetSymbolAddress((void**)&d_xh, g_xh);
    __half* d_hh;  cudaGetSymbolAddress((void**)&d_hh, g_hh);
    __half* d_zh;  cudaGetSymbolAddress((void**)&d_zh, g_zh);
    __half* d_wt;  cudaGetSymbolAddress((void**)&d_wt, g_WhT);

    // 1. prep: convert x + W, count degrees, reset cursors
    prep_kernel<<<(NN * DD / 4 + 255) / 256, 256>>>(x, W, ei);
    // 2. inv + block-local CSR region allocation
    scanlocal_kernel<<<dim3(NBLK, RR), 256>>>();
    // 3. fill CSR
    fill_csr_kernel<<<(RR * E4 + 255) / 256, 256>>>(ei);

    dim3 agg_grid((NN * 32 + 255) / 256, RR);
    int gemm_grid = (NN + 127) / 128;
    const __half* z0 = d_zh;
    const __half* z1 = d_zh + NN * DD;

    // 4-5. layer 0
    agg_kernel<<<agg_grid, 256>>>(d_xh);
    gemm_dual_mma<<<gemm_grid, 256>>>(d_wt + 0 * DD * DD, d_wt + 1 * DD * DD,
                                      b + 0 * DD, b + 1 * DD, z0, z1, d_hh, 1, nullptr);
    // 6-7. layer 1 (+ fused mean-pool partial sums)
    agg_kernel<<<agg_grid, 256>>>(d_hh);
    gemm_dual_mma<<<gemm_grid, 256>>>(d_wt + 2 * DD * DD, d_wt + 3 * DD * DD,
                                      b + 2 * DD, b + 3 * DD, z0, z1, d_xh, 0, batch);

    // 8. pool finalize + head (+ invariant re-zero)
    pool2_kernel<<<GG, DD>>>(batch, lin_w, lin_b, out);
}

// round 15
// speedup vs baseline: 1.0452x; 1.0452x over previous
#include <cuda_runtime.h>
#include <cuda_fp16.h>

#define NN 50000
#define EE 800000
#define RR 2
#define DD 128
#define GG 64
#define CC 8
#define NBLK ((NN + 255) / 256)   // 196
#define E4 (EE / 4)               // 200000

// ---------------- scratch ----------------------------------------------------
// NOTE: g_deg and g_gsum rely on a cross-launch invariant: statically
// zero-initialized at module load, and re-zeroed by pool2 at the END of every
// kernel_launch. Deterministic: every call sees them zeroed on entry.
__device__ __half g_xh[NN * DD];         // fp16 x; later reused for final h
__device__ __half g_hh[NN * DD];         // fp16 layer-1 activations
__device__ __half g_zh[RR][NN * DD];     // per-relation aggregated (fp16)
__device__ __half g_WhT[RR * 2][DD * DD];// fp16 transposed weights [n][k]
__device__ float  g_inv[RR][NN];
__device__ int    g_deg[RR][NN];         // zeroed by pool2 (invariant)
__device__ int    g_rowptr[RR][NN];      // per-node region begin
__device__ int    g_fill[RR][NN];        // fill cursor; == region end after fill
__device__ int2   g_edge[RR][EE];        // {src, float norm}
__device__ int    g_cursor[RR];          // region allocation cursors
__device__ float  g_gsum[GG * DD];       // pooled partial sums (zeroed by pool2)

// ---------------- 1. prep: convert x + W, count degrees, reset cursors -------
__global__ void prep_kernel(const float* __restrict__ x, const float* __restrict__ W,
                            const int* __restrict__ ei) {
    int i = blockIdx.x * blockDim.x + threadIdx.x;
    if (i < 2) g_cursor[i] = 0;
    if (i < NN * DD / 4) {
        float4 v = ((const float4*)x)[i];
        __half2 a = __floats2half2_rn(v.x, v.y);
        __half2 b = __floats2half2_rn(v.z, v.w);
        uint2 o;
        o.x = *(unsigned*)&a;
        o.y = *(unsigned*)&b;
        ((uint2*)g_xh)[i] = o;
    }
    if (i < 4 * DD * DD) {   // W [L,R,D,D] (k,n) -> WhT[lr][n*D+k]
        int lr = i >> 14, rem = i & 16383, k = rem >> 7, n = rem & 127;
        g_WhT[lr][n * DD + k] = __float2half(W[i]);
    }
    if (i < RR * E4) {       // degree count (g_deg zeroed by invariant)
        int r = i / E4, e4 = i % E4;
        int4 d = __ldg(&((const int4*)(ei + r * 2 * EE + EE))[e4]);
        atomicAdd(&g_deg[r][d.x], 1);
        atomicAdd(&g_deg[r][d.y], 1);
        atomicAdd(&g_deg[r][d.z], 1);
        atomicAdd(&g_deg[r][d.w], 1);
    }
}

// ---------------- 2. local scan: inv sqrt + block-local CSR regions ----------
__global__ void scanlocal_kernel() {
    int r = blockIdx.y, blk = blockIdx.x, t = threadIdx.x;
    int idx = blk * 256 + t;
    int v = (idx < NN) ? g_deg[r][idx] : 0;
    if (idx < NN) g_inv[r][idx] = rsqrtf((float)v + 1.0f);

    int lane = t & 31, w = t >> 5;
    int x = v;
    #pragma unroll
    for (int o = 1; o < 32; o <<= 1) {
        int y = __shfl_up_sync(~0u, x, o);
        if (lane >= o) x += y;
    }
    __shared__ int wsum[8];
    __shared__ int sbase;
    if (lane == 31) wsum[w] = x;
    __syncthreads();
    if (t == 0) {
        int run = 0;
        #pragma unroll
        for (int i = 0; i < 8; i++) { int tmp = wsum[i]; wsum[i] = run; run += tmp; }
        sbase = atomicAdd(&g_cursor[r], run);
    }
    __syncthreads();
    int exc = x - v + wsum[w] + sbase;
    if (idx < NN) { g_rowptr[r][idx] = exc; g_fill[r][idx] = exc; }
}

// ---------------- 3. fill CSR (4 edges / thread) -----------------------------
__global__ void fill_csr_kernel(const int* __restrict__ ei) {
    int idx = blockIdx.x * blockDim.x + threadIdx.x;
    if (idx >= RR * E4) return;
    int r = idx / E4, e4 = idx % E4;
    int4 s = __ldg(&((const int4*)(ei + r * 2 * EE))[e4]);
    int4 d = __ldg(&((const int4*)(ei + r * 2 * EE + EE))[e4]);
    const float* inv = g_inv[r];
    int2* ed = g_edge[r];
    int p;
    p = atomicAdd(&g_fill[r][d.x], 1);
    ed[p] = make_int2(s.x, __float_as_int(inv[s.x] * inv[d.x]));
    p = atomicAdd(&g_fill[r][d.y], 1);
    ed[p] = make_int2(s.y, __float_as_int(inv[s.y] * inv[d.y]));
    p = atomicAdd(&g_fill[r][d.z], 1);
    ed[p] = make_int2(s.z, __float_as_int(inv[s.z] * inv[d.z]));
    p = atomicAdd(&g_fill[r][d.w], 1);
    ed[p] = make_int2(s.w, __float_as_int(inv[s.w] * inv[d.w]));
}

// ---------------- 4/6. aggregation: z_r = A_r_norm h + d^-1 h ----------------
// One warp per dst node; lane owns 4 channels; fp32 FFMA accumulate, fp16 store.
// Feature gathers: __ldcg (L2-only). Edge stream: int2 (L1-friendly broadcast).
// Block = 128 threads (4 nodes/CTA); grid.x = NN*32/128 = 12500.
__global__ __launch_bounds__(128) void agg_kernel(const __half* __restrict__ h) {
    int r = blockIdx.y;
    int gw = (blockIdx.x * blockDim.x + threadIdx.x) >> 5;
    int lane = threadIdx.x & 31;
    if (gw >= NN) return;
    const uint2* hv = (const uint2*)h;
    const int2* ed = g_edge[r];
    float4 acc = make_float4(0.f, 0.f, 0.f, 0.f);
    int beg = g_rowptr[r][gw], end = g_fill[r][gw];
    int e = beg;
    for (; e + 8 <= end; e += 8) {
        int2 p[8]; uint2 v[8];
        #pragma unroll
        for (int u = 0; u < 8; u++) p[u] = __ldcs(&ed[e + u]);
        #pragma unroll
        for (int u = 0; u < 8; u++) v[u] = __ldcg(&hv[p[u].x * 32 + lane]);
        #pragma unroll
        for (int u = 0; u < 8; u++) {
            float nm = __int_as_float(p[u].y);
            float2 fa = __half22float2(*(__half2*)&v[u].x);
            float2 fb = __half22float2(*(__half2*)&v[u].y);
            acc.x = fmaf(nm, fa.x, acc.x);
            acc.y = fmaf(nm, fa.y, acc.y);
            acc.z = fmaf(nm, fb.x, acc.z);
            acc.w = fmaf(nm, fb.y, acc.w);
        }
    }
    for (; e + 2 <= end; e += 2) {
        int2 p0 = __ldcs(&ed[e]);
        int2 p1 = __ldcs(&ed[e + 1]);
        uint2 v0 = __ldcg(&hv[p0.x * 32 + lane]);
        uint2 v1 = __ldcg(&hv[p1.x * 32 + lane]);
        float n0 = __int_as_float(p0.y), n1 = __int_as_float(p1.y);
        float2 a0 = __half22float2(*(__half2*)&v0.x), b0 = __half22float2(*(__half2*)&v0.y);
        float2 a1 = __half22float2(*(__half2*)&v1.x), b1 = __half22float2(*(__half2*)&v1.y);
        acc.x = fmaf(n0, a0.x, fmaf(n1, a1.x, acc.x));
        acc.y = fmaf(n0, a0.y, fmaf(n1, a1.y, acc.y));
        acc.z = fmaf(n0, b0.x, fmaf(n1, b1.x, acc.z));
        acc.w = fmaf(n0, b0.y, fmaf(n1, b1.y, acc.w));
    }
    if (e < end) {
        int2 p = __ldcs(&ed[e]);
        uint2 v = __ldcg(&hv[p.x * 32 + lane]);
        float nm = __int_as_float(p.y);
        float2 fa = __half22float2(*(__half2*)&v.x);
        float2 fb = __half22float2(*(__half2*)&v.y);
        acc.x = fmaf(nm, fa.x, acc.x);
        acc.y = fmaf(nm, fa.y, acc.y);
        acc.z = fmaf(nm, fb.x, acc.z);
        acc.w = fmaf(nm, fb.y, acc.w);
    }
    float iv = g_inv[r][gw];
    float self = iv * iv;
    uint2 v = __ldcg(&hv[gw * 32 + lane]);
    float2 fa = __half22float2(*(__half2*)&v.x);
    float2 fb = __half22float2(*(__half2*)&v.y);
    acc.x = fmaf(self, fa.x, acc.x);
    acc.y = fmaf(self, fa.y, acc.y);
    acc.z = fmaf(self, fb.x, acc.z);
    acc.w = fmaf(self, fb.y, acc.w);
    __half2 o0 = __floats2half2_rn(acc.x, acc.y);
    __half2 o1 = __floats2half2_rn(acc.z, acc.w);
    uint2 o;
    o.x = *(unsigned*)&o0;
    o.y = *(unsigned*)&o1;
    ((uint2*)g_zh[r])[gw * 32 + lane] = o;
}

// ---------------- 5/7. fused dual tensor-core GEMM (+ optional pool) ---------
__global__ __launch_bounds__(256) void gemm_dual_mma(
    const __half* __restrict__ WT0, const __half* __restrict__ WT1,
    const float* __restrict__ b0, const float* __restrict__ b1,
    const __half* __restrict__ zh0, const __half* __restrict__ zh1,
    __half* __restrict__ outh, int do_relu, const int* __restrict__ batch)
{
    __shared__ __half SBUF[2 * 128 * 72];   // As | Bs ; reused as h tile for pool
    __half (*As)[72] = (__half(*)[72])SBUF;
    __half (*Bs)[72] = (__half(*)[72])(SBUF + 128 * 72);
    int t = threadIdx.x;
    int warp = t >> 5, lane = t & 31;
    int wm = warp & 3, wn = warp >> 2;
    int g = lane >> 2, tg = lane & 3;
    int row0 = blockIdx.x * 128;

    float acc[2][8][4];
    #pragma unroll
    for (int mt = 0; mt < 2; mt++)
        #pragma unroll
        for (int nt = 0; nt < 8; nt++)
            #pragma unroll
            for (int q = 0; q < 4; q++) acc[mt][nt][q] = 0.f;

    #pragma unroll
    for (int phase = 0; phase < 2; phase++) {
        const __half* Z  = phase ? zh1 : zh0;
        const __half* WT = phase ? WT1 : WT0;
        #pragma unroll
        for (int kc = 0; kc < 128; kc += 64) {
            __syncthreads();
            for (int i = t; i < 128 * 8; i += 256) {
                int row = i >> 3, c8 = (i & 7) * 8;
                uint4 v = make_uint4(0, 0, 0, 0);
                int gr = row0 + row;
                if (gr < NN) v = *(const uint4*)&Z[gr * 128 + kc + c8];
                *(uint4*)&As[row][c8] = v;
            }
            for (int i = t; i < 128 * 8; i += 256) {
                int n = i >> 3, c8 = (i & 7) * 8;
                *(uint4*)&Bs[n][c8] = *(const uint4*)&WT[n * 128 + kc + c8];
            }
            __syncthreads();
            #pragma unroll
            for (int kk = 0; kk < 4; kk++) {
                int k0 = kk * 16;
                unsigned a[2][4];
                #pragma unroll
                for (int mt = 0; mt < 2; mt++) {
                    int rb = wm * 32 + mt * 16;
                    a[mt][0] = *(unsigned*)&As[rb + g][k0 + tg * 2];
                    a[mt][1] = *(unsigned*)&As[rb + g + 8][k0 + tg * 2];
                    a[mt][2] = *(unsigned*)&As[rb + g][k0 + tg * 2 + 8];
                    a[mt][3] = *(unsigned*)&As[rb + g + 8][k0 + tg * 2 + 8];
                }
                #pragma unroll
                for (int nt = 0; nt < 8; nt++) {
                    int cb = wn * 64 + nt * 8 + g;
                    unsigned bf0 = *(unsigned*)&Bs[cb][k0 + tg * 2];
                    unsigned bf1 = *(unsigned*)&Bs[cb][k0 + tg * 2 + 8];
                    #pragma unroll
                    for (int mt = 0; mt < 2; mt++) {
                        asm volatile(
                            "mma.sync.aligned.m16n8k16.row.col.f32.f16.f16.f32 "
                            "{%0,%1,%2,%3}, {%4,%5,%6,%7}, {%8,%9}, {%0,%1,%2,%3};\n"
                            : "+f"(acc[mt][nt][0]), "+f"(acc[mt][nt][1]),
                              "+f"(acc[mt][nt][2]), "+f"(acc[mt][nt][3])
                            : "r"(a[mt][0]), "r"(a[mt][1]), "r"(a[mt][2]), "r"(a[mt][3]),
                              "r"(bf0), "r"(bf1));
                    }
                }
            }
        }
    }
    if (batch) __syncthreads();

    #pragma unroll
    for (int mt = 0; mt < 2; mt++) {
        int rl = wm * 32 + mt * 16 + g;
        int r_lo = row0 + rl;
        int r_hi = r_lo + 8;
        #pragma unroll
        for (int nt = 0; nt < 8; nt++) {
            int c = wn * 64 + nt * 8 + tg * 2;
            float bia0 = b0[c] + b1[c];
            float bia1 = b0[c + 1] + b1[c + 1];
            float v0 = acc[mt][nt][0] + bia0;
            float v1 = acc[mt][nt][1] + bia1;
            float v2 = acc[mt][nt][2] + bia0;
            float v3 = acc[mt][nt][3] + bia1;
            if (do_relu) {
                v0 = fmaxf(v0, 0.f); v1 = fmaxf(v1, 0.f);
                v2 = fmaxf(v2, 0.f); v3 = fmaxf(v3, 0.f);
            }
            __half2 plo = __floats2half2_rn(v0, v1);
            __half2 phi = __floats2half2_rn(v2, v3);
            if (r_lo < NN) *(__half2*)&outh[r_lo * 128 + c] = plo;
            if (r_hi < NN) *(__half2*)&outh[r_hi * 128 + c] = phi;
            if (batch) {
                *(__half2*)&SBUF[rl * 130 + c] = plo;
                *(__half2*)&SBUF[(rl + 8) * 130 + c] = phi;
            }
        }
    }
    if (batch) {
        __syncthreads();
        if (t < DD) {
            int row_end = (row0 + 128 > NN) ? (NN - row0) : 128;
            float run = 0.f;
            int cur = __ldg(&batch[row0]);
            for (int rl = 0; rl < row_end; rl++) {
                int gid = __ldg(&batch[row0 + rl]);
                if (gid != cur) {
                    atomicAdd(&g_gsum[cur * DD + t], run);
                    run = 0.f;
                    cur = gid;
                }
                run += __half2float(SBUF[rl * 130 + t]);
            }
            atomicAdd(&g_gsum[cur * DD + t], run);
        }
    }
}

// ---------------- 8. pool finalize + head + re-zero invariants ---------------
__global__ void pool2_kernel(const int* __restrict__ batch,
                             const float* __restrict__ lw, const float* __restrict__ lb,
                             float* __restrict__ out) {
    int g = blockIdx.x;
    int t = threadIdx.x;
    int lo = 0, hi = NN;
    while (lo < hi) { int m = (lo + hi) >> 1; if (batch[m] < g) lo = m + 1; else hi = m; }
    int beg = lo;
    lo = beg; hi = NN;
    while (lo < hi) { int m = (lo + hi) >> 1; if (batch[m] < g + 1) lo = m + 1; else hi = m; }
    int cnt = lo - beg;

    __shared__ float pooled[DD];
    float s = g_gsum[g * DD + t];
    g_gsum[g * DD + t] = 0.f;              // re-zero own slot (invariant)
    pooled[t] = s / fmaxf((float)cnt, 1.0f);
    __syncthreads();
    if (t < CC) {
        float o = lb[t];
        #pragma unroll 16
        for (int d = 0; d < DD; d++) o = fmaf(pooled[d], lw[d * CC + t], o);
        out[g * CC + t] = o;
    }
    // re-zero degree counters for next launch (disjoint from reads above)
    for (int i = blockIdx.x * blockDim.x + t; i < RR * NN; i += GG * DD)
        ((int*)g_deg)[i] = 0;
}

// ---------------- host launch -------------------------------------------------
extern "C" void kernel_launch(void* const* d_in, const int* in_sizes, int n_in,
                              void* d_out, int out_size)
{
    const float* x     = (const float*)d_in[0];
    const float* W     = (const float*)d_in[1];
    const float* b     = (const float*)d_in[2];
    const float* lin_w = (const float*)d_in[3];
    const float* lin_b = (const float*)d_in[4];
    const int*   ei    = (const int*)d_in[5];
    const int*   batch = (const int*)d_in[6];
    float* out = (float*)d_out;

    __half* d_xh;  cudaGetSymbolAddress((void**)&d_xh, g_xh);
    __half* d_hh;  cudaGetSymbolAddress((void**)&d_hh, g_hh);
    __half* d_zh;  cudaGetSymbolAddress((void**)&d_zh, g_zh);
    __half* d_wt;  cudaGetSymbolAddress((void**)&d_wt, g_WhT);

    // 1. prep: convert x + W, count degrees, reset cursors
    prep_kernel<<<(NN * DD / 4 + 255) / 256, 256>>>(x, W, ei);
    // 2. inv + block-local CSR region allocation
    scanlocal_kernel<<<dim3(NBLK, RR), 256>>>();
    // 3. fill CSR
    fill_csr_kernel<<<(RR * E4 + 255) / 256, 256>>>(ei);

    dim3 agg_grid((NN * 32 + 127) / 128, RR);   // 12500 blocks, 4 nodes each
    int gemm_grid = (NN + 127) / 128;
    const __half* z0 = d_zh;
    const __half* z1 = d_zh + NN * DD;

    // 4-5. layer 0
    agg_kernel<<<agg_grid, 128>>>(d_xh);
    gemm_dual_mma<<<gemm_grid, 256>>>(d_wt + 0 * DD * DD, d_wt + 1 * DD * DD,
                                      b + 0 * DD, b + 1 * DD, z0, z1, d_hh, 1, nullptr);
    // 6-7. layer 1 (+ fused mean-pool partial sums)
    agg_kernel<<<agg_grid, 128>>>(d_hh);
    gemm_dual_mma<<<gemm_grid, 256>>>(d_wt + 2 * DD * DD, d_wt + 3 * DD * DD,
                                      b + 2 * DD, b + 3 * DD, z0, z1, d_xh, 0, batch);

    // 8. pool finalize + head (+ invariant re-zero)
    pool2_kernel<<<GG, DD>>>(batch, lin_w, lin_b, out);
}